// round 15
// baseline (speedup 1.0000x reference)
#include <cuda_runtime.h>
#include <cuda_fp16.h>
#include <math.h>
#include <stdint.h>

#define BB   4
#define NN   4096
#define DIN  256
#define DOUT 128

// ---------------- scratch (__device__ globals: allocation-free) -------------
__device__ float  g_h  [BB * NN * DOUT];        // 8 MB : h = x @ W ([b][i][d])
__device__ __half g_p  [(size_t)BB * NN * NN];  // 134 MB : masked exp scores
__device__ __half g_hpT[BB * DOUT * NN];        // 4 MB : fp16 clamp(iz_j*h)^T
__device__ float  g_wh1[BB * NN];
__device__ float  g_wh2[BB * NN];
__device__ int    g_mw1i[BB];                   // ordered-int encoded max(wh1)
__device__ float  g_pz [BB * 32 * NN];          // partial col-sums (32 i-blocks)
__device__ float  g_ss [BB * DOUT];             // per-(b,d) sum of squares

__device__ __forceinline__ float gelu_f(float x) {
    return 0.5f * x * (1.0f + erff(x * 0.70710678118654752f));
}
__device__ __forceinline__ float ex2f(float x) {
    float r; asm("ex2.approx.ftz.f32 %0, %1;" : "=f"(r) : "f"(x)); return r;
}
__device__ __forceinline__ void mma_f16(float* d, const uint32_t* a, const uint32_t* b) {
    asm volatile("mma.sync.aligned.m16n8k16.row.col.f32.f16.f16.f32 "
                 "{%0,%1,%2,%3}, {%4,%5,%6,%7}, {%8,%9}, {%0,%1,%2,%3};"
                 : "+f"(d[0]), "+f"(d[1]), "+f"(d[2]), "+f"(d[3])
                 : "r"(a[0]), "r"(a[1]), "r"(a[2]), "r"(a[3]),
                   "r"(b[0]), "r"(b[1]));
}
__device__ __forceinline__ uint32_t smem_u32(const void* p) {
    uint32_t a;
    asm("{ .reg .u64 t; cvta.to.shared.u64 t, %1; cvt.u32.u64 %0, t; }" : "=r"(a) : "l"(p));
    return a;
}
#define LDMATRIX_X4(r0, r1, r2, r3, addr) \
    asm volatile("ldmatrix.sync.aligned.m8n8.x4.shared.b16 {%0,%1,%2,%3}, [%4];" \
                 : "=r"(r0), "=r"(r1), "=r"(r2), "=r"(r3) : "r"(addr))
#define LDMATRIX_X2(r0, r1, addr) \
    asm volatile("ldmatrix.sync.aligned.m8n8.x2.shared.b16 {%0,%1}, [%2];" \
                 : "=r"(r0), "=r"(r1) : "r"(addr))

// ---------------- K1: h = x @ W  (fp32 FFMA, full precision) ----------------
// Block 0 additionally re-initializes g_ss / g_mw1i EVERY call (graph replay
// safety): strided loop covers ALL BB*DOUT entries with 256 threads.
__global__ __launch_bounds__(256) void k1_h(const float* __restrict__ x,
                                            const float* __restrict__ w) {
    __shared__ float xsT[32 * 129];
    __shared__ float ws[32 * 128];
    const int t = threadIdx.x, lane = t & 31, wrp = t >> 5;
    const int ty = t >> 4, tx = t & 15;
    const int i0 = blockIdx.x * 128;

    if (blockIdx.x == 0) {
        for (int ii = t; ii < BB * DOUT; ii += 256) g_ss[ii] = 0.0f;   // all 512
        if (t < BB) g_mw1i[t] = __float_as_int(-1e30f) ^ 0x7fffffff;
    }

    float acc[8][8];
#pragma unroll
    for (int r = 0; r < 8; r++)
#pragma unroll
        for (int c = 0; c < 8; c++) acc[r][c] = 0.0f;

    for (int kk = 0; kk < DIN; kk += 32) {
#pragma unroll
        for (int s = 0; s < 16; s++) {
            int ii = wrp + 8 * s;
            xsT[lane * 129 + ii] = x[(i0 + ii) * DIN + kk + lane];
        }
#pragma unroll
        for (int s = 0; s < 16; s++) {
            int idx = t + s * 256;
            int k = idx >> 7, d = idx & 127;
            ws[k * 128 + d] = w[(kk + k) * DOUT + d];
        }
        __syncthreads();
#pragma unroll
        for (int k = 0; k < 32; k++) {
            float aa[8];
#pragma unroll
            for (int r = 0; r < 8; r++) aa[r] = xsT[k * 129 + ty * 8 + r];
            float4 b0 = *(const float4*)&ws[k * 128 + tx * 8];
            float4 b1 = *(const float4*)&ws[k * 128 + tx * 8 + 4];
            float bb[8] = {b0.x, b0.y, b0.z, b0.w, b1.x, b1.y, b1.z, b1.w};
#pragma unroll
            for (int r = 0; r < 8; r++)
#pragma unroll
                for (int c = 0; c < 8; c++)
                    acc[r][c] = fmaf(aa[r], bb[c], acc[r][c]);
        }
        __syncthreads();
    }
#pragma unroll
    for (int r = 0; r < 8; r++) {
        int row = i0 + ty * 8 + r;
        float4 o0, o1;
        o0.x = acc[r][0]; o0.y = acc[r][1]; o0.z = acc[r][2]; o0.w = acc[r][3];
        o1.x = acc[r][4]; o1.y = acc[r][5]; o1.z = acc[r][6]; o1.w = acc[r][7];
        *(float4*)&g_h[row * DOUT + tx * 8]     = o0;
        *(float4*)&g_h[row * DOUT + tx * 8 + 4] = o1;
    }
}

// ---------------- K1b: Wh1/Wh2 per row + fused batch max (atomicMax) --------
__global__ __launch_bounds__(256) void k1b_wh(const float* __restrict__ a) {
    const int t = threadIdx.x, lane = t & 31, wrp = t >> 5;
    const int row = blockIdx.x * 8 + wrp;          // 0..16383
    float4 hv = *(const float4*)&g_h[(size_t)row * DOUT + lane * 4];
    float4 a1 = *(const float4*)&a[lane * 4];
    float4 a2 = *(const float4*)&a[DOUT + lane * 4];
    float s1 = hv.x * a1.x + hv.y * a1.y + hv.z * a1.z + hv.w * a1.w;
    float s2 = hv.x * a2.x + hv.y * a2.y + hv.z * a2.z + hv.w * a2.w;
#pragma unroll
    for (int o = 16; o > 0; o >>= 1) {
        s1 += __shfl_xor_sync(0xffffffffu, s1, o);
        s2 += __shfl_xor_sync(0xffffffffu, s2, o);
    }
    if (lane == 0) {
        g_wh1[row] = s1; g_wh2[row] = s2;
        int k = __float_as_int(s1);
        k = (k >= 0) ? k : (k ^ 0x7fffffff);
        atomicMax(&g_mw1i[row >> 12], k);          // order-independent: deterministic
    }
}

// ---------------- P1: scores -> masked exp (fp16) + partial col sums --------
// E = ex2( u + u*t - c2 ),  u = 0.5*log2e*s,  t = erf(s/sqrt2),  c2 = log2e*c.
__global__ __launch_bounds__(256) void p1_scores(const int* __restrict__ adj) {
    __shared__ float wh1s[128];
    __shared__ float zred[8 * 128];
    const int t = threadIdx.x, tx = t & 31, ty = t >> 5;
    const int b = blockIdx.z, bN = b * NN;
    const int j0 = blockIdx.x * 128, i0 = blockIdx.y * 128;
    const int jj = j0 + 4 * tx;
    int mk = g_mw1i[b];
    if (mk < 0) mk ^= 0x7fffffff;                  // decode
    const float mw = __int_as_float(mk);
    const float HL2E = 0.72134752044448f;          // 0.5*log2(e)
    const float L2E  = 1.44269504088896f;

    float wh2v[4], c2[4], z[4];
#pragma unroll
    for (int u = 0; u < 4; u++) {
        wh2v[u] = g_wh2[bN + jj + u];
        c2[u]   = L2E * fmaxf(0.0f, mw + wh2v[u]); // >= log2e*gelu(s) for all i
        z[u]    = 0.0f;
    }
    if (t < 128) wh1s[t] = g_wh1[bN + i0 + t];
    __syncthreads();

    const int4* ap = (const int4*)(adj + (size_t)(bN + i0) * NN) + (jj >> 2);
#pragma unroll 4
    for (int r = 0; r < 16; r++) {
        const int i = i0 + ty + 8 * r;
        const float w1 = wh1s[ty + 8 * r];
        int4 a4 = ap[(size_t)(ty + 8 * r) * (NN >> 2)];
        float e[4];
#pragma unroll
        for (int u = 0; u < 4; u++) {
            float s  = w1 + wh2v[u];
            float uu = HL2E * s;
            float tt = erff(s * 0.70710678118654752f);
            e[u] = ex2f(fmaf(uu, tt, uu - c2[u]));
        }
        e[0] = (a4.x > 0) ? e[0] : 0.0f;
        e[1] = (a4.y > 0) ? e[1] : 0.0f;
        e[2] = (a4.z > 0) ? e[2] : 0.0f;
        e[3] = (a4.w > 0) ? e[3] : 0.0f;
        z[0] += e[0]; z[1] += e[1]; z[2] += e[2]; z[3] += e[3];
        __half2 p01 = __floats2half2_rn(e[0], e[1]);
        __half2 p23 = __floats2half2_rn(e[2], e[3]);
        uint2 pw;
        pw.x = *(uint32_t*)&p01;
        pw.y = *(uint32_t*)&p23;
        *(uint2*)(g_p + (size_t)(bN + i) * NN + jj) = pw;
    }
#pragma unroll
    for (int u = 0; u < 4; u++) zred[ty * 128 + 4 * tx + u] = z[u];
    __syncthreads();
    if (t < 128) {
        float s = 0.0f;
#pragma unroll
        for (int u = 0; u < 8; u++) s += zred[u * 128 + t];
        g_pz[(b * 32 + blockIdx.y) * NN + j0 + t] = s;
    }
}

// ---------------- K2c: fused iz + transpose-scale -> g_hpT ------------------
__global__ __launch_bounds__(256) void k2c() {
    __shared__ float zp[32][9];
    __shared__ float izs[32];
    __shared__ float ts[32][33];
    const int t = threadIdx.x;
    const int b = blockIdx.y, j0 = blockIdx.x * 32;
    {
        const int jl = t >> 3, u = t & 7;
        float s = 0.0f;
#pragma unroll
        for (int c = 0; c < 4; c++)
            s += g_pz[(b * 32 + u * 4 + c) * NN + j0 + jl];
        zp[jl][u] = s;
    }
    __syncthreads();
    if (t < 32) {
        float S = 0.0f;
#pragma unroll
        for (int u = 0; u < 8; u++) S += zp[t][u];
        izs[t] = 1.0f / fmaxf(S, 1e-30f);
    }
    __syncthreads();
    const int lx = t & 31, ly = t >> 5;
#pragma unroll
    for (int d0 = 0; d0 < DOUT; d0 += 32) {
#pragma unroll
        for (int s = 0; s < 4; s++)
            ts[ly + 8 * s][lx] = g_h[(size_t)(b * NN + j0 + ly + 8 * s) * DOUT + d0 + lx];
        __syncthreads();
#pragma unroll
        for (int s = 0; s < 4; s++) {
            float v = ts[lx][ly + 8 * s] * izs[lx];
            v = fminf(fmaxf(v, -60000.0f), 60000.0f);   // never inf in fp16
            g_hpT[(size_t)(b * DOUT + d0 + ly + 8 * s) * NN + j0 + lx] = __float2half(v);
        }
        __syncthreads();
    }
}

// ---------------- K3: out = gelu(E @ h') — fp16 HMMA, K-chunk 128 -----------
// Block 64(i) x 128(d), K chunks of 128 -> 32 iterations, 32 barriers.
// 8 warps (2m x 4n), warp 32x32 as 2x4 m16n8k16 x 8 ks-steps.
// Rows padded to 136 halves (272 B): row-stride = 68 banks = 4 mod 32, the
// same conflict-free residue class as the proven pad-72 layout for both
// ldmatrix phases; STS phases hit 32 distinct banks.
// SMEM: stage = A(64x136) + B(128x136) = 26112 halves; 2 stages = 104448 B.
#define PADH 136
#define B_OFF 8704
#define STGH 26112
#define SMEM_K3 104448

__global__ __launch_bounds__(256, 2) void k3_pv(float* __restrict__ out) {
    extern __shared__ __half sm[];
    const uint32_t sbase = smem_u32(sm);
    const int t = threadIdx.x, lane = t & 31, wrp = t >> 5;
    const int g = lane >> 2, tg = lane & 3;
    const int b = blockIdx.y, bN = b * NN;
    const int i0 = blockIdx.x * 64;
    const int m_base = (wrp >> 2) * 32;
    const int n_base = (wrp & 3) * 32;
    const int rowA = m_base + (lane & 15);
    const int colA = (lane >> 4) << 3;
    const int rowB = n_base + (lane & 7);
    const int colB = lane & 8;
    // staging: thread t covers row (t>>4) + 16*s, 8-half segment (t&15)
    const int srow = t >> 4, sseg = t & 15;
    const __half* gA = g_p   + (size_t)(bN + i0 + srow) * NN + sseg * 8;
    const __half* gB = g_hpT + (size_t)(b * DOUT + srow) * NN + sseg * 8;
    __half* stA = sm + srow * PADH + sseg * 8;
    __half* stB = sm + B_OFF + srow * PADH + sseg * 8;

    float acc[2][4][4];
#pragma unroll
    for (int mt = 0; mt < 2; mt++)
#pragma unroll
        for (int nt = 0; nt < 4; nt++)
#pragma unroll
            for (int q = 0; q < 4; q++) acc[mt][nt][q] = 0.0f;

    // fill stage 0 (kb = 0): A 64 rows (4x16), B 128 rows (8x16)
#pragma unroll
    for (int s = 0; s < 4; s++)
        *(uint4*)(stA + s * 16 * PADH) = *(const uint4*)(gA + (size_t)(s * 16) * NN);
#pragma unroll
    for (int s = 0; s < 8; s++)
        *(uint4*)(stB + s * 16 * PADH) = *(const uint4*)(gB + (size_t)(s * 16) * NN);
    __syncthreads();

    for (int kt = 0; kt < 32; kt++) {
        const int cur = kt & 1;
        if (kt + 1 < 32) {                         // overlap fill with mma
            const int kb = (kt + 1) * 128;
            __half* dA = sm + (cur ? 0 : STGH) + srow * PADH + sseg * 8;
            __half* dB = dA + B_OFF;
#pragma unroll
            for (int s = 0; s < 4; s++)
                *(uint4*)(dA + s * 16 * PADH) = *(const uint4*)(gA + kb + (size_t)(s * 16) * NN);
#pragma unroll
            for (int s = 0; s < 8; s++)
                *(uint4*)(dB + s * 16 * PADH) = *(const uint4*)(gB + kb + (size_t)(s * 16) * NN);
        }
        const uint32_t sA = sbase + (cur ? STGH : 0) * 2;
        const uint32_t sB = sA + B_OFF * 2;
#pragma unroll
        for (int ks = 0; ks < 8; ks++) {
            const int k0 = ks * 16;
            uint32_t af[2][4], bf[4][2];
#pragma unroll
            for (int mt = 0; mt < 2; mt++)
                LDMATRIX_X4(af[mt][0], af[mt][1], af[mt][2], af[mt][3],
                            sA + ((rowA + mt * 16) * PADH + k0 + colA) * 2);
#pragma unroll
            for (int nt = 0; nt < 4; nt++)
                LDMATRIX_X2(bf[nt][0], bf[nt][1],
                            sB + ((rowB + nt * 8) * PADH + k0 + colB) * 2);
#pragma unroll
            for (int mt = 0; mt < 2; mt++)
#pragma unroll
                for (int nt = 0; nt < 4; nt++)
                    mma_f16(acc[mt][nt], af[mt], bf[nt]);
        }
        __syncthreads();
    }

#pragma unroll
    for (int mt = 0; mt < 2; mt++) {
        int r = i0 + m_base + mt * 16 + g;
#pragma unroll
        for (int nt = 0; nt < 4; nt++) {
            int cl = n_base + nt * 8 + 2 * tg;
            float2 v0, v1;
            v0.x = gelu_f(acc[mt][nt][0]); v0.y = gelu_f(acc[mt][nt][1]);
            v1.x = gelu_f(acc[mt][nt][2]); v1.y = gelu_f(acc[mt][nt][3]);
            *(float2*)&out[(size_t)(bN + r) * DOUT + cl]     = v0;
            *(float2*)&out[(size_t)(bN + r + 8) * DOUT + cl] = v1;
        }
    }
}

// ---------------- K4: sum of squares over node axis per (b,d) ---------------
__global__ __launch_bounds__(128) void k4_sumsq(const float* __restrict__ out) {
    const int t = threadIdx.x;
    const int b = blockIdx.y;
    const int ibase = blockIdx.x * 64;
    float s = 0.0f;
    for (int i = 0; i < 64; i++) {
        float v = out[(size_t)(b * NN + ibase + i) * DOUT + t];
        s += v * v;
    }
    atomicAdd(&g_ss[b * DOUT + t], s);
}

// ---------------- K5: L2-normalize over node axis + bias --------------------
__global__ __launch_bounds__(256) void k5_norm(float* __restrict__ out,
                                               const float* __restrict__ bias) {
    int idx = blockIdx.x * 256 + threadIdx.x;
    int d = idx & 127;
    int b = idx >> 19;
    float ss = g_ss[b * DOUT + d];
    float inv = 1.0f / fmaxf(sqrtf(ss), 1e-12f);
    out[idx] = out[idx] * inv + bias[d];
}

// ---------------- launch ----------------------------------------------------
extern "C" void kernel_launch(void* const* d_in, const int* in_sizes, int n_in,
                              void* d_out, int out_size) {
    const float* x    = (const float*)d_in[0];   // [4,4096,256]
    const int*   adj  = (const int*)d_in[1];     // [4,4096,4096]
    const float* w    = (const float*)d_in[2];   // [256,128]
    const float* a    = (const float*)d_in[3];   // [256,1]
    const float* bias = (const float*)d_in[4];   // [128]
    float* out = (float*)d_out;                  // [4,4096,128] fp32

    cudaFuncSetAttribute(k3_pv, cudaFuncAttributeMaxDynamicSharedMemorySize, SMEM_K3);

    k1_h<<<128, 256>>>(x, w);
    k1b_wh<<<2048, 256>>>(a);
    p1_scores<<<dim3(NN / 128, NN / 128, BB), 256>>>(adj);
    k2c<<<dim3(NN / 32, BB), 256>>>();
    k3_pv<<<dim3(NN / 64, BB), 256, SMEM_K3>>>(out);
    k4_sumsq<<<dim3(64, BB), 128>>>(out);
    k5_norm<<<8192, 256>>>(out, bias);
}

// round 16
// speedup vs baseline: 1.0438x; 1.0438x over previous
#include <cuda_runtime.h>
#include <cuda_fp16.h>
#include <math.h>
#include <stdint.h>

#define BB   4
#define NN   4096
#define DIN  256
#define DOUT 128

// ---------------- scratch (__device__ globals: allocation-free) -------------
__device__ float  g_h  [BB * NN * DOUT];        // 8 MB : h = x @ W ([b][i][d])
__device__ __half g_p  [(size_t)BB * NN * NN];  // 134 MB : masked exp scores
__device__ __half g_hpT[BB * DOUT * NN];        // 4 MB : fp16 clamp(iz_j*h)^T
__device__ float  g_wh1[BB * NN];
__device__ float  g_wh2[BB * NN];
__device__ int    g_mw1i[BB];                   // ordered-int encoded max(wh1)
__device__ float  g_pz [BB * 32 * NN];          // partial col-sums (32 i-blocks)
__device__ float  g_ss [BB * DOUT];             // per-(b,d) sum of squares

__device__ __forceinline__ float gelu_f(float x) {
    return 0.5f * x * (1.0f + erff(x * 0.70710678118654752f));
}
__device__ __forceinline__ float ex2f(float x) {
    float r; asm("ex2.approx.ftz.f32 %0, %1;" : "=f"(r) : "f"(x)); return r;
}
__device__ __forceinline__ void mma_f16(float* d, const uint32_t* a, const uint32_t* b) {
    asm volatile("mma.sync.aligned.m16n8k16.row.col.f32.f16.f16.f32 "
                 "{%0,%1,%2,%3}, {%4,%5,%6,%7}, {%8,%9}, {%0,%1,%2,%3};"
                 : "+f"(d[0]), "+f"(d[1]), "+f"(d[2]), "+f"(d[3])
                 : "r"(a[0]), "r"(a[1]), "r"(a[2]), "r"(a[3]),
                   "r"(b[0]), "r"(b[1]));
}
__device__ __forceinline__ uint32_t smem_u32(const void* p) {
    uint32_t a;
    asm("{ .reg .u64 t; cvta.to.shared.u64 t, %1; cvt.u32.u64 %0, t; }" : "=r"(a) : "l"(p));
    return a;
}
#define LDMATRIX_X4(r0, r1, r2, r3, addr) \
    asm volatile("ldmatrix.sync.aligned.m8n8.x4.shared.b16 {%0,%1,%2,%3}, [%4];" \
                 : "=r"(r0), "=r"(r1), "=r"(r2), "=r"(r3) : "r"(addr))
#define LDMATRIX_X2(r0, r1, addr) \
    asm volatile("ldmatrix.sync.aligned.m8n8.x2.shared.b16 {%0,%1}, [%2];" \
                 : "=r"(r0), "=r"(r1) : "r"(addr))

// ---------------- K1: h = x @ W  (fp32 FFMA, full precision) ----------------
// Block 0 additionally re-initializes g_ss / g_mw1i EVERY call (graph replay
// safety): strided loop covers ALL BB*DOUT entries with 256 threads.
__global__ __launch_bounds__(256) void k1_h(const float* __restrict__ x,
                                            const float* __restrict__ w) {
    __shared__ float xsT[32 * 129];
    __shared__ float ws[32 * 128];
    const int t = threadIdx.x, lane = t & 31, wrp = t >> 5;
    const int ty = t >> 4, tx = t & 15;
    const int i0 = blockIdx.x * 128;

    if (blockIdx.x == 0) {
        for (int ii = t; ii < BB * DOUT; ii += 256) g_ss[ii] = 0.0f;   // all 512
        if (t < BB) g_mw1i[t] = __float_as_int(-1e30f) ^ 0x7fffffff;
    }

    float acc[8][8];
#pragma unroll
    for (int r = 0; r < 8; r++)
#pragma unroll
        for (int c = 0; c < 8; c++) acc[r][c] = 0.0f;

    for (int kk = 0; kk < DIN; kk += 32) {
#pragma unroll
        for (int s = 0; s < 16; s++) {
            int ii = wrp + 8 * s;
            xsT[lane * 129 + ii] = x[(i0 + ii) * DIN + kk + lane];
        }
#pragma unroll
        for (int s = 0; s < 16; s++) {
            int idx = t + s * 256;
            int k = idx >> 7, d = idx & 127;
            ws[k * 128 + d] = w[(kk + k) * DOUT + d];
        }
        __syncthreads();
#pragma unroll
        for (int k = 0; k < 32; k++) {
            float aa[8];
#pragma unroll
            for (int r = 0; r < 8; r++) aa[r] = xsT[k * 129 + ty * 8 + r];
            float4 b0 = *(const float4*)&ws[k * 128 + tx * 8];
            float4 b1 = *(const float4*)&ws[k * 128 + tx * 8 + 4];
            float bb[8] = {b0.x, b0.y, b0.z, b0.w, b1.x, b1.y, b1.z, b1.w};
#pragma unroll
            for (int r = 0; r < 8; r++)
#pragma unroll
                for (int c = 0; c < 8; c++)
                    acc[r][c] = fmaf(aa[r], bb[c], acc[r][c]);
        }
        __syncthreads();
    }
#pragma unroll
    for (int r = 0; r < 8; r++) {
        int row = i0 + ty * 8 + r;
        float4 o0, o1;
        o0.x = acc[r][0]; o0.y = acc[r][1]; o0.z = acc[r][2]; o0.w = acc[r][3];
        o1.x = acc[r][4]; o1.y = acc[r][5]; o1.z = acc[r][6]; o1.w = acc[r][7];
        *(float4*)&g_h[row * DOUT + tx * 8]     = o0;
        *(float4*)&g_h[row * DOUT + tx * 8 + 4] = o1;
    }
}

// ---------------- K1b: Wh1/Wh2 per row + fused batch max (atomicMax) --------
__global__ __launch_bounds__(256) void k1b_wh(const float* __restrict__ a) {
    const int t = threadIdx.x, lane = t & 31, wrp = t >> 5;
    const int row = blockIdx.x * 8 + wrp;          // 0..16383
    float4 hv = *(const float4*)&g_h[(size_t)row * DOUT + lane * 4];
    float4 a1 = *(const float4*)&a[lane * 4];
    float4 a2 = *(const float4*)&a[DOUT + lane * 4];
    float s1 = hv.x * a1.x + hv.y * a1.y + hv.z * a1.z + hv.w * a1.w;
    float s2 = hv.x * a2.x + hv.y * a2.y + hv.z * a2.z + hv.w * a2.w;
#pragma unroll
    for (int o = 16; o > 0; o >>= 1) {
        s1 += __shfl_xor_sync(0xffffffffu, s1, o);
        s2 += __shfl_xor_sync(0xffffffffu, s2, o);
    }
    if (lane == 0) {
        g_wh1[row] = s1; g_wh2[row] = s2;
        int k = __float_as_int(s1);
        k = (k >= 0) ? k : (k ^ 0x7fffffff);
        atomicMax(&g_mw1i[row >> 12], k);          // order-independent: deterministic
    }
}

// ---------------- P1: scores -> masked exp (fp16) + partial col sums --------
// E = ex2( u + u*t - c2 ),  u = 0.5*log2e*s,  t = erf(s/sqrt2),  c2 = log2e*c.
__global__ __launch_bounds__(256) void p1_scores(const int* __restrict__ adj) {
    __shared__ float wh1s[128];
    __shared__ float zred[8 * 128];
    const int t = threadIdx.x, tx = t & 31, ty = t >> 5;
    const int b = blockIdx.z, bN = b * NN;
    const int j0 = blockIdx.x * 128, i0 = blockIdx.y * 128;
    const int jj = j0 + 4 * tx;
    int mk = g_mw1i[b];
    if (mk < 0) mk ^= 0x7fffffff;                  // decode
    const float mw = __int_as_float(mk);
    const float HL2E = 0.72134752044448f;          // 0.5*log2(e)
    const float L2E  = 1.44269504088896f;

    float wh2v[4], c2[4], z[4];
#pragma unroll
    for (int u = 0; u < 4; u++) {
        wh2v[u] = g_wh2[bN + jj + u];
        c2[u]   = L2E * fmaxf(0.0f, mw + wh2v[u]); // >= log2e*gelu(s) for all i
        z[u]    = 0.0f;
    }
    if (t < 128) wh1s[t] = g_wh1[bN + i0 + t];
    __syncthreads();

    const int4* ap = (const int4*)(adj + (size_t)(bN + i0) * NN) + (jj >> 2);
#pragma unroll 4
    for (int r = 0; r < 16; r++) {
        const int i = i0 + ty + 8 * r;
        const float w1 = wh1s[ty + 8 * r];
        int4 a4 = ap[(size_t)(ty + 8 * r) * (NN >> 2)];
        float e[4];
#pragma unroll
        for (int u = 0; u < 4; u++) {
            float s  = w1 + wh2v[u];
            float uu = HL2E * s;
            float tt = erff(s * 0.70710678118654752f);
            e[u] = ex2f(fmaf(uu, tt, uu - c2[u]));
        }
        e[0] = (a4.x > 0) ? e[0] : 0.0f;
        e[1] = (a4.y > 0) ? e[1] : 0.0f;
        e[2] = (a4.z > 0) ? e[2] : 0.0f;
        e[3] = (a4.w > 0) ? e[3] : 0.0f;
        z[0] += e[0]; z[1] += e[1]; z[2] += e[2]; z[3] += e[3];
        __half2 p01 = __floats2half2_rn(e[0], e[1]);
        __half2 p23 = __floats2half2_rn(e[2], e[3]);
        uint2 pw;
        pw.x = *(uint32_t*)&p01;
        pw.y = *(uint32_t*)&p23;
        *(uint2*)(g_p + (size_t)(bN + i) * NN + jj) = pw;
    }
#pragma unroll
    for (int u = 0; u < 4; u++) zred[ty * 128 + 4 * tx + u] = z[u];
    __syncthreads();
    if (t < 128) {
        float s = 0.0f;
#pragma unroll
        for (int u = 0; u < 8; u++) s += zred[u * 128 + t];
        g_pz[(b * 32 + blockIdx.y) * NN + j0 + t] = s;
    }
}

// ---------------- K2c: fused iz + transpose-scale -> g_hpT ------------------
__global__ __launch_bounds__(256) void k2c() {
    __shared__ float zp[32][9];
    __shared__ float izs[32];
    __shared__ float ts[32][33];
    const int t = threadIdx.x;
    const int b = blockIdx.y, j0 = blockIdx.x * 32;
    {
        const int jl = t >> 3, u = t & 7;
        float s = 0.0f;
#pragma unroll
        for (int c = 0; c < 4; c++)
            s += g_pz[(b * 32 + u * 4 + c) * NN + j0 + jl];
        zp[jl][u] = s;
    }
    __syncthreads();
    if (t < 32) {
        float S = 0.0f;
#pragma unroll
        for (int u = 0; u < 8; u++) S += zp[t][u];
        izs[t] = 1.0f / fmaxf(S, 1e-30f);
    }
    __syncthreads();
    const int lx = t & 31, ly = t >> 5;
#pragma unroll
    for (int d0 = 0; d0 < DOUT; d0 += 32) {
#pragma unroll
        for (int s = 0; s < 4; s++)
            ts[ly + 8 * s][lx] = g_h[(size_t)(b * NN + j0 + ly + 8 * s) * DOUT + d0 + lx];
        __syncthreads();
#pragma unroll
        for (int s = 0; s < 4; s++) {
            float v = ts[lx][ly + 8 * s] * izs[lx];
            v = fminf(fmaxf(v, -60000.0f), 60000.0f);   // never inf in fp16
            g_hpT[(size_t)(b * DOUT + d0 + ly + 8 * s) * NN + j0 + lx] = __float2half(v);
        }
        __syncthreads();
    }
}

// ---------------- K3: out = gelu(E @ h') — fp16 HMMA, K-chunk 64 ------------
// EXACT R14 (246.5us) mainloop. Block 64(i) x 128(d), K chunks of 64.
// 8 warps (2m x 4n), warp 32x32 as 2x4 m16n8k16 x 4 ks-steps.
// Rows padded to 72 halves (144 B): conflict-free staging + ldmatrix.
// SMEM: stage = A(64x72) + B(128x72) = 13824 halves; 2 stages = 55296 B.
// NEW: k4 fused into epilogue — per-block ssq reduce (SMEM reused after the
// final barrier) + 128 global atomicAdds; k4 kernel deleted.
#define PADH 72
#define B_OFF 4608
#define STGH 13824
#define SMEM_K3 55296

__global__ __launch_bounds__(256, 2) void k3_pv(float* __restrict__ out) {
    extern __shared__ __half sm[];
    const uint32_t sbase = smem_u32(sm);
    const int t = threadIdx.x, lane = t & 31, wrp = t >> 5;
    const int g = lane >> 2, tg = lane & 3;
    const int b = blockIdx.y, bN = b * NN;
    const int i0 = blockIdx.x * 64;
    const int m_base = (wrp >> 2) * 32;
    const int n_base = (wrp & 3) * 32;
    const int rowA = m_base + (lane & 15);
    const int colA = (lane >> 4) << 3;
    const int rowB = n_base + (lane & 7);
    const int colB = lane & 8;
    // staging: thread t covers row (t>>3) + 32*s, 8-half segment (t&7)
    const int srow = t >> 3, sseg = t & 7;
    const __half* gA = g_p   + (size_t)(bN + i0 + srow) * NN + sseg * 8;
    const __half* gB = g_hpT + (size_t)(b * DOUT + srow) * NN + sseg * 8;
    __half* stA = sm + srow * PADH + sseg * 8;
    __half* stB = sm + B_OFF + srow * PADH + sseg * 8;

    float acc[2][4][4];
#pragma unroll
    for (int mt = 0; mt < 2; mt++)
#pragma unroll
        for (int nt = 0; nt < 4; nt++)
#pragma unroll
            for (int q = 0; q < 4; q++) acc[mt][nt][q] = 0.0f;

    // fill stage 0 (kb = 0)
#pragma unroll
    for (int s = 0; s < 2; s++)
        *(uint4*)(stA + s * 32 * PADH) = *(const uint4*)(gA + (size_t)(s * 32) * NN);
#pragma unroll
    for (int s = 0; s < 4; s++)
        *(uint4*)(stB + s * 32 * PADH) = *(const uint4*)(gB + (size_t)(s * 32) * NN);
    __syncthreads();

    for (int kt = 0; kt < 64; kt++) {
        const int cur = kt & 1;
        if (kt + 1 < 64) {                         // overlap fill with mma
            const int kb = (kt + 1) * 64;
            __half* dA = sm + (cur ? 0 : STGH) + srow * PADH + sseg * 8;
            __half* dB = dA + B_OFF;
#pragma unroll
            for (int s = 0; s < 2; s++)
                *(uint4*)(dA + s * 32 * PADH) = *(const uint4*)(gA + kb + (size_t)(s * 32) * NN);
#pragma unroll
            for (int s = 0; s < 4; s++)
                *(uint4*)(dB + s * 32 * PADH) = *(const uint4*)(gB + kb + (size_t)(s * 32) * NN);
        }
        const uint32_t sA = sbase + (cur ? STGH : 0) * 2;
        const uint32_t sB = sA + B_OFF * 2;
#pragma unroll
        for (int ks = 0; ks < 4; ks++) {
            const int k0 = ks * 16;
            uint32_t af[2][4], bf[4][2];
#pragma unroll
            for (int mt = 0; mt < 2; mt++)
                LDMATRIX_X4(af[mt][0], af[mt][1], af[mt][2], af[mt][3],
                            sA + ((rowA + mt * 16) * PADH + k0 + colA) * 2);
#pragma unroll
            for (int nt = 0; nt < 4; nt++)
                LDMATRIX_X2(bf[nt][0], bf[nt][1],
                            sB + ((rowB + nt * 8) * PADH + k0 + colB) * 2);
#pragma unroll
            for (int mt = 0; mt < 2; mt++)
#pragma unroll
                for (int nt = 0; nt < 4; nt++)
                    mma_f16(acc[mt][nt], af[mt], bf[nt]);
        }
        __syncthreads();
    }

    // epilogue: gelu + stores + fused per-(b,d) sum-of-squares.
    // Staging SMEM is dead after the loop's final barrier -> reuse as ssq[128].
    float* ssq = (float*)sm;
    if (t < 128) ssq[t] = 0.0f;
    __syncthreads();
#pragma unroll
    for (int nt = 0; nt < 4; nt++) {
        const int cl = n_base + nt * 8 + 2 * tg;
        float s0 = 0.0f, s1 = 0.0f;
#pragma unroll
        for (int mt = 0; mt < 2; mt++) {
            int r = i0 + m_base + mt * 16 + g;
            float2 v0, v1;
            v0.x = gelu_f(acc[mt][nt][0]); v0.y = gelu_f(acc[mt][nt][1]);
            v1.x = gelu_f(acc[mt][nt][2]); v1.y = gelu_f(acc[mt][nt][3]);
            *(float2*)&out[(size_t)(bN + r) * DOUT + cl]     = v0;
            *(float2*)&out[(size_t)(bN + r + 8) * DOUT + cl] = v1;
            s0 += v0.x * v0.x + v1.x * v1.x;
            s1 += v0.y * v0.y + v1.y * v1.y;
        }
        atomicAdd(&ssq[cl],     s0);
        atomicAdd(&ssq[cl + 1], s1);
    }
    __syncthreads();
    if (t < 128) atomicAdd(&g_ss[b * DOUT + t], ssq[t]);
}

// ---------------- K5: L2-normalize over node axis + bias --------------------
__global__ __launch_bounds__(256) void k5_norm(float* __restrict__ out,
                                               const float* __restrict__ bias) {
    int idx = blockIdx.x * 256 + threadIdx.x;
    int d = idx & 127;
    int b = idx >> 19;
    float ss = g_ss[b * DOUT + d];
    float inv = 1.0f / fmaxf(sqrtf(ss), 1e-12f);
    out[idx] = out[idx] * inv + bias[d];
}

// ---------------- launch ----------------------------------------------------
extern "C" void kernel_launch(void* const* d_in, const int* in_sizes, int n_in,
                              void* d_out, int out_size) {
    const float* x    = (const float*)d_in[0];   // [4,4096,256]
    const int*   adj  = (const int*)d_in[1];     // [4,4096,4096]
    const float* w    = (const float*)d_in[2];   // [256,128]
    const float* a    = (const float*)d_in[3];   // [256,1]
    const float* bias = (const float*)d_in[4];   // [128]
    float* out = (float*)d_out;                  // [4,4096,128] fp32

    cudaFuncSetAttribute(k3_pv, cudaFuncAttributeMaxDynamicSharedMemorySize, SMEM_K3);

    k1_h<<<128, 256>>>(x, w);
    k1b_wh<<<2048, 256>>>(a);
    p1_scores<<<dim3(NN / 128, NN / 128, BB), 256>>>(adj);
    k2c<<<dim3(NN / 32, BB), 256>>>();
    k3_pv<<<dim3(NN / 64, BB), 256, SMEM_K3>>>(out);
    k5_norm<<<8192, 256>>>(out, bias);
}

// round 17
// speedup vs baseline: 1.1660x; 1.1171x over previous
#include <cuda_runtime.h>
#include <cuda_fp16.h>
#include <math.h>
#include <stdint.h>

#define BB   4
#define NN   4096
#define DIN  256
#define DOUT 128

// ---------------- scratch (__device__ globals: allocation-free) -------------
__device__ float  g_h  [BB * NN * DOUT];        // 8 MB : h = x @ W ([b][i][d])
__device__ __half g_p  [(size_t)BB * NN * NN];  // 134 MB : masked exp scores
__device__ __half g_hpT[BB * DOUT * NN];        // 4 MB : fp16 clamp(iz_j*h)^T
__device__ float  g_wh1[BB * NN];
__device__ float  g_wh2[BB * NN];
__device__ int    g_mw1i[BB];                   // ordered-int encoded max(wh1)
__device__ float  g_pz [BB * 32 * NN];          // partial col-sums (32 i-blocks)
__device__ float  g_ss [BB * DOUT];             // per-(b,d) sum of squares

__device__ __forceinline__ float gelu_f(float x) {
    return 0.5f * x * (1.0f + erff(x * 0.70710678118654752f));
}
__device__ __forceinline__ float ex2f(float x) {
    float r; asm("ex2.approx.ftz.f32 %0, %1;" : "=f"(r) : "f"(x)); return r;
}
__device__ __forceinline__ void mma_f16(float* d, const uint32_t* a, const uint32_t* b) {
    asm volatile("mma.sync.aligned.m16n8k16.row.col.f32.f16.f16.f32 "
                 "{%0,%1,%2,%3}, {%4,%5,%6,%7}, {%8,%9}, {%0,%1,%2,%3};"
                 : "+f"(d[0]), "+f"(d[1]), "+f"(d[2]), "+f"(d[3])
                 : "r"(a[0]), "r"(a[1]), "r"(a[2]), "r"(a[3]),
                   "r"(b[0]), "r"(b[1]));
}
__device__ __forceinline__ uint32_t smem_u32(const void* p) {
    uint32_t a;
    asm("{ .reg .u64 t; cvta.to.shared.u64 t, %1; cvt.u32.u64 %0, t; }" : "=r"(a) : "l"(p));
    return a;
}
#define LDMATRIX_X4(r0, r1, r2, r3, addr) \
    asm volatile("ldmatrix.sync.aligned.m8n8.x4.shared.b16 {%0,%1,%2,%3}, [%4];" \
                 : "=r"(r0), "=r"(r1), "=r"(r2), "=r"(r3) : "r"(addr))
#define LDMATRIX_X2(r0, r1, addr) \
    asm volatile("ldmatrix.sync.aligned.m8n8.x2.shared.b16 {%0,%1}, [%2];" \
                 : "=r"(r0), "=r"(r1) : "r"(addr))
#define CP_ASYNC16(dst, src) \
    asm volatile("cp.async.ca.shared.global [%0], [%1], 16;" :: "r"(dst), "l"(src))
#define CP_COMMIT() asm volatile("cp.async.commit_group;" ::: "memory")
#define CP_WAIT1()  asm volatile("cp.async.wait_group 1;" ::: "memory")
#define CP_WAIT0()  asm volatile("cp.async.wait_group 0;" ::: "memory")

// ---------------- K1: h = x @ W  (fp32 FFMA, full precision) ----------------
// Block 0 additionally re-initializes g_ss / g_mw1i EVERY call (graph replay
// safety): strided loop covers ALL BB*DOUT entries with 256 threads.
__global__ __launch_bounds__(256) void k1_h(const float* __restrict__ x,
                                            const float* __restrict__ w) {
    __shared__ float xsT[32 * 129];
    __shared__ float ws[32 * 128];
    const int t = threadIdx.x, lane = t & 31, wrp = t >> 5;
    const int ty = t >> 4, tx = t & 15;
    const int i0 = blockIdx.x * 128;

    if (blockIdx.x == 0) {
        for (int ii = t; ii < BB * DOUT; ii += 256) g_ss[ii] = 0.0f;   // all 512
        if (t < BB) g_mw1i[t] = __float_as_int(-1e30f) ^ 0x7fffffff;
    }

    float acc[8][8];
#pragma unroll
    for (int r = 0; r < 8; r++)
#pragma unroll
        for (int c = 0; c < 8; c++) acc[r][c] = 0.0f;

    for (int kk = 0; kk < DIN; kk += 32) {
#pragma unroll
        for (int s = 0; s < 16; s++) {
            int ii = wrp + 8 * s;
            xsT[lane * 129 + ii] = x[(i0 + ii) * DIN + kk + lane];
        }
#pragma unroll
        for (int s = 0; s < 16; s++) {
            int idx = t + s * 256;
            int k = idx >> 7, d = idx & 127;
            ws[k * 128 + d] = w[(kk + k) * DOUT + d];
        }
        __syncthreads();
#pragma unroll
        for (int k = 0; k < 32; k++) {
            float aa[8];
#pragma unroll
            for (int r = 0; r < 8; r++) aa[r] = xsT[k * 129 + ty * 8 + r];
            float4 b0 = *(const float4*)&ws[k * 128 + tx * 8];
            float4 b1 = *(const float4*)&ws[k * 128 + tx * 8 + 4];
            float bb[8] = {b0.x, b0.y, b0.z, b0.w, b1.x, b1.y, b1.z, b1.w};
#pragma unroll
            for (int r = 0; r < 8; r++)
#pragma unroll
                for (int c = 0; c < 8; c++)
                    acc[r][c] = fmaf(aa[r], bb[c], acc[r][c]);
        }
        __syncthreads();
    }
#pragma unroll
    for (int r = 0; r < 8; r++) {
        int row = i0 + ty * 8 + r;
        float4 o0, o1;
        o0.x = acc[r][0]; o0.y = acc[r][1]; o0.z = acc[r][2]; o0.w = acc[r][3];
        o1.x = acc[r][4]; o1.y = acc[r][5]; o1.z = acc[r][6]; o1.w = acc[r][7];
        *(float4*)&g_h[row * DOUT + tx * 8]     = o0;
        *(float4*)&g_h[row * DOUT + tx * 8 + 4] = o1;
    }
}

// ---------------- K1b: Wh1/Wh2 per row + fused batch max (atomicMax) --------
__global__ __launch_bounds__(256) void k1b_wh(const float* __restrict__ a) {
    const int t = threadIdx.x, lane = t & 31, wrp = t >> 5;
    const int row = blockIdx.x * 8 + wrp;          // 0..16383
    float4 hv = *(const float4*)&g_h[(size_t)row * DOUT + lane * 4];
    float4 a1 = *(const float4*)&a[lane * 4];
    float4 a2 = *(const float4*)&a[DOUT + lane * 4];
    float s1 = hv.x * a1.x + hv.y * a1.y + hv.z * a1.z + hv.w * a1.w;
    float s2 = hv.x * a2.x + hv.y * a2.y + hv.z * a2.z + hv.w * a2.w;
#pragma unroll
    for (int o = 16; o > 0; o >>= 1) {
        s1 += __shfl_xor_sync(0xffffffffu, s1, o);
        s2 += __shfl_xor_sync(0xffffffffu, s2, o);
    }
    if (lane == 0) {
        g_wh1[row] = s1; g_wh2[row] = s2;
        int k = __float_as_int(s1);
        k = (k >= 0) ? k : (k ^ 0x7fffffff);
        atomicMax(&g_mw1i[row >> 12], k);          // order-independent: deterministic
    }
}

// ---------------- P1: scores -> masked exp (fp16) + partial col sums --------
// E = ex2( u + u*t - c2 ),  u = 0.5*log2e*s,  t = erf(s/sqrt2),  c2 = log2e*c.
__global__ __launch_bounds__(256) void p1_scores(const int* __restrict__ adj) {
    __shared__ float wh1s[128];
    __shared__ float zred[8 * 128];
    const int t = threadIdx.x, tx = t & 31, ty = t >> 5;
    const int b = blockIdx.z, bN = b * NN;
    const int j0 = blockIdx.x * 128, i0 = blockIdx.y * 128;
    const int jj = j0 + 4 * tx;
    int mk = g_mw1i[b];
    if (mk < 0) mk ^= 0x7fffffff;                  // decode
    const float mw = __int_as_float(mk);
    const float HL2E = 0.72134752044448f;          // 0.5*log2(e)
    const float L2E  = 1.44269504088896f;

    float wh2v[4], c2[4], z[4];
#pragma unroll
    for (int u = 0; u < 4; u++) {
        wh2v[u] = g_wh2[bN + jj + u];
        c2[u]   = L2E * fmaxf(0.0f, mw + wh2v[u]); // >= log2e*gelu(s) for all i
        z[u]    = 0.0f;
    }
    if (t < 128) wh1s[t] = g_wh1[bN + i0 + t];
    __syncthreads();

    const int4* ap = (const int4*)(adj + (size_t)(bN + i0) * NN) + (jj >> 2);
#pragma unroll 4
    for (int r = 0; r < 16; r++) {
        const int i = i0 + ty + 8 * r;
        const float w1 = wh1s[ty + 8 * r];
        int4 a4 = ap[(size_t)(ty + 8 * r) * (NN >> 2)];
        float e[4];
#pragma unroll
        for (int u = 0; u < 4; u++) {
            float s  = w1 + wh2v[u];
            float uu = HL2E * s;
            float tt = erff(s * 0.70710678118654752f);
            e[u] = ex2f(fmaf(uu, tt, uu - c2[u]));
        }
        e[0] = (a4.x > 0) ? e[0] : 0.0f;
        e[1] = (a4.y > 0) ? e[1] : 0.0f;
        e[2] = (a4.z > 0) ? e[2] : 0.0f;
        e[3] = (a4.w > 0) ? e[3] : 0.0f;
        z[0] += e[0]; z[1] += e[1]; z[2] += e[2]; z[3] += e[3];
        __half2 p01 = __floats2half2_rn(e[0], e[1]);
        __half2 p23 = __floats2half2_rn(e[2], e[3]);
        uint2 pw;
        pw.x = *(uint32_t*)&p01;
        pw.y = *(uint32_t*)&p23;
        *(uint2*)(g_p + (size_t)(bN + i) * NN + jj) = pw;
    }
#pragma unroll
    for (int u = 0; u < 4; u++) zred[ty * 128 + 4 * tx + u] = z[u];
    __syncthreads();
    if (t < 128) {
        float s = 0.0f;
#pragma unroll
        for (int u = 0; u < 8; u++) s += zred[u * 128 + t];
        g_pz[(b * 32 + blockIdx.y) * NN + j0 + t] = s;
    }
}

// ---------------- K2c: fused iz + transpose-scale -> g_hpT ------------------
__global__ __launch_bounds__(256) void k2c() {
    __shared__ float zp[32][9];
    __shared__ float izs[32];
    __shared__ float ts[32][33];
    const int t = threadIdx.x;
    const int b = blockIdx.y, j0 = blockIdx.x * 32;
    {
        const int jl = t >> 3, u = t & 7;
        float s = 0.0f;
#pragma unroll
        for (int c = 0; c < 4; c++)
            s += g_pz[(b * 32 + u * 4 + c) * NN + j0 + jl];
        zp[jl][u] = s;
    }
    __syncthreads();
    if (t < 32) {
        float S = 0.0f;
#pragma unroll
        for (int u = 0; u < 8; u++) S += zp[t][u];
        izs[t] = 1.0f / fmaxf(S, 1e-30f);
    }
    __syncthreads();
    const int lx = t & 31, ly = t >> 5;
#pragma unroll
    for (int d0 = 0; d0 < DOUT; d0 += 32) {
#pragma unroll
        for (int s = 0; s < 4; s++)
            ts[ly + 8 * s][lx] = g_h[(size_t)(b * NN + j0 + ly + 8 * s) * DOUT + d0 + lx];
        __syncthreads();
#pragma unroll
        for (int s = 0; s < 4; s++) {
            float v = ts[lx][ly + 8 * s] * izs[lx];
            v = fminf(fmaxf(v, -60000.0f), 60000.0f);   // never inf in fp16
            g_hpT[(size_t)(b * DOUT + d0 + ly + 8 * s) * NN + j0 + lx] = __float2half(v);
        }
        __syncthreads();
    }
}

// ---------------- K3: out = gelu(E @ h') — fp16 HMMA, K-64, cp.async x3 -----
// R14/R16 mainloop geometry (proven): block 64(i) x 128(d), K chunks of 64,
// 8 warps (2m x 4n), warp 32x32, rows padded to 72 halves.
// DELTA vs R16: synchronous LDG->STS staging replaced by a 3-stage
// cp.async.ca ring (prefetch distance 2 iters ~ covers DRAM latency; no
// register staging, no data-dependent stall in the issuing thread).
// SMEM: 3 stages x 13824 halves = 82944 B; 2 CTAs/SM = 166 KB.
#define PADH 72
#define B_OFF 4608
#define STGH 13824
#define SMEM_K3 82944

__global__ __launch_bounds__(256, 2) void k3_pv(float* __restrict__ out) {
    extern __shared__ __half sm[];
    const uint32_t sbase = smem_u32(sm);
    const int t = threadIdx.x, lane = t & 31, wrp = t >> 5;
    const int g = lane >> 2, tg = lane & 3;
    const int b = blockIdx.y, bN = b * NN;
    const int i0 = blockIdx.x * 64;
    const int m_base = (wrp >> 2) * 32;
    const int n_base = (wrp & 3) * 32;
    const int rowA = m_base + (lane & 15);
    const int colA = (lane >> 4) << 3;
    const int rowB = n_base + (lane & 7);
    const int colB = lane & 8;
    // staging: thread t covers row (t>>3) + 32*s, 8-half segment (t&7)
    const int srow = t >> 3, sseg = t & 7;
    const __half* gA = g_p   + (size_t)(bN + i0 + srow) * NN + sseg * 8;
    const __half* gB = g_hpT + (size_t)(b * DOUT + srow) * NN + sseg * 8;
    const uint32_t dA0 = sbase + (uint32_t)(srow * PADH + sseg * 8) * 2;
    const uint32_t dB0 = dA0 + B_OFF * 2;

    float acc[2][4][4];
#pragma unroll
    for (int mt = 0; mt < 2; mt++)
#pragma unroll
        for (int nt = 0; nt < 4; nt++)
#pragma unroll
            for (int q = 0; q < 4; q++) acc[mt][nt][q] = 0.0f;

    // prologue: prefetch stages 0,1 (kb = 0, 64)
#pragma unroll
    for (int p = 0; p < 2; p++) {
        const int kb = p * 64;
        const uint32_t so = (uint32_t)(p * STGH) * 2;
#pragma unroll
        for (int s = 0; s < 2; s++)
            CP_ASYNC16(dA0 + so + (uint32_t)(s * 32 * PADH) * 2,
                       gA + kb + (size_t)(s * 32) * NN);
#pragma unroll
        for (int s = 0; s < 4; s++)
            CP_ASYNC16(dB0 + so + (uint32_t)(s * 32 * PADH) * 2,
                       gB + kb + (size_t)(s * 32) * NN);
        CP_COMMIT();
    }

    for (int kt = 0; kt < 64; kt++) {
        const int stg = kt % 3;
        CP_WAIT1();                 // stage kt resident (only kt+1's group may pend)
        __syncthreads();            // all warps done reading stage (kt+2)%3 (iter kt-1)
        if (kt + 2 < 64) {          // prefetch kt+2 into stage (kt+2)%3
            const int kb = (kt + 2) * 64;
            const uint32_t so = (uint32_t)(((kt + 2) % 3) * STGH) * 2;
#pragma unroll
            for (int s = 0; s < 2; s++)
                CP_ASYNC16(dA0 + so + (uint32_t)(s * 32 * PADH) * 2,
                           gA + kb + (size_t)(s * 32) * NN);
#pragma unroll
            for (int s = 0; s < 4; s++)
                CP_ASYNC16(dB0 + so + (uint32_t)(s * 32 * PADH) * 2,
                           gB + kb + (size_t)(s * 32) * NN);
        }
        CP_COMMIT();                // one group per iteration (possibly empty)
        const uint32_t sA = sbase + (uint32_t)(stg * STGH) * 2;
        const uint32_t sB = sA + B_OFF * 2;
#pragma unroll
        for (int ks = 0; ks < 4; ks++) {
            const int k0 = ks * 16;
            uint32_t af[2][4], bf[4][2];
#pragma unroll
            for (int mt = 0; mt < 2; mt++)
                LDMATRIX_X4(af[mt][0], af[mt][1], af[mt][2], af[mt][3],
                            sA + (uint32_t)((rowA + mt * 16) * PADH + k0 + colA) * 2);
#pragma unroll
            for (int nt = 0; nt < 4; nt++)
                LDMATRIX_X2(bf[nt][0], bf[nt][1],
                            sB + (uint32_t)((rowB + nt * 8) * PADH + k0 + colB) * 2);
#pragma unroll
            for (int mt = 0; mt < 2; mt++)
#pragma unroll
                for (int nt = 0; nt < 4; nt++)
                    mma_f16(acc[mt][nt], af[mt], bf[nt]);
        }
    }
    CP_WAIT0();                     // drain trailing (empty) groups
    __syncthreads();

    // epilogue: gelu + stores + fused per-(b,d) sum-of-squares.
    // Staging SMEM is dead after the barrier above -> reuse as ssq[128].
    float* ssq = (float*)sm;
    if (t < 128) ssq[t] = 0.0f;
    __syncthreads();
#pragma unroll
    for (int nt = 0; nt < 4; nt++) {
        const int cl = n_base + nt * 8 + 2 * tg;
        float s0 = 0.0f, s1 = 0.0f;
#pragma unroll
        for (int mt = 0; mt < 2; mt++) {
            int r = i0 + m_base + mt * 16 + g;
            float2 v0, v1;
            v0.x = gelu_f(acc[mt][nt][0]); v0.y = gelu_f(acc[mt][nt][1]);
            v1.x = gelu_f(acc[mt][nt][2]); v1.y = gelu_f(acc[mt][nt][3]);
            *(float2*)&out[(size_t)(bN + r) * DOUT + cl]     = v0;
            *(float2*)&out[(size_t)(bN + r + 8) * DOUT + cl] = v1;
            s0 += v0.x * v0.x + v1.x * v1.x;
            s1 += v0.y * v0.y + v1.y * v1.y;
        }
        atomicAdd(&ssq[cl],     s0);
        atomicAdd(&ssq[cl + 1], s1);
    }
    __syncthreads();
    if (t < 128) atomicAdd(&g_ss[b * DOUT + t], ssq[t]);
}

// ---------------- K5: L2-normalize over node axis + bias --------------------
__global__ __launch_bounds__(256) void k5_norm(float* __restrict__ out,
                                               const float* __restrict__ bias) {
    int idx = blockIdx.x * 256 + threadIdx.x;
    int d = idx & 127;
    int b = idx >> 19;
    float ss = g_ss[b * DOUT + d];
    float inv = 1.0f / fmaxf(sqrtf(ss), 1e-12f);
    out[idx] = out[idx] * inv + bias[d];
}

// ---------------- launch ----------------------------------------------------
extern "C" void kernel_launch(void* const* d_in, const int* in_sizes, int n_in,
                              void* d_out, int out_size) {
    const float* x    = (const float*)d_in[0];   // [4,4096,256]
    const int*   adj  = (const int*)d_in[1];     // [4,4096,4096]
    const float* w    = (const float*)d_in[2];   // [256,128]
    const float* a    = (const float*)d_in[3];   // [256,1]
    const float* bias = (const float*)d_in[4];   // [128]
    float* out = (float*)d_out;                  // [4,4096,128] fp32

    cudaFuncSetAttribute(k3_pv, cudaFuncAttributeMaxDynamicSharedMemorySize, SMEM_K3);

    k1_h<<<128, 256>>>(x, w);
    k1b_wh<<<2048, 256>>>(a);
    p1_scores<<<dim3(NN / 128, NN / 128, BB), 256>>>(adj);
    k2c<<<dim3(NN / 32, BB), 256>>>();
    k3_pv<<<dim3(NN / 64, BB), 256, SMEM_K3>>>(out);
    k5_norm<<<8192, 256>>>(out, bias);
}